// round 10
// baseline (speedup 1.0000x reference)
#include <cuda_runtime.h>
#include <cuda_bf16.h>
#include <math.h>
#include <stdint.h>

#ifndef M_PI
#define M_PI 3.14159265358979323846
#endif

#define FULLMASK 0xffffffffu

// ---------------- scratch (static device globals; no allocations) ----------------
__device__ float2   g_F[16777216];    // packed spectrum Z = fft2(x1 + i x2), shifted  [1024 pairs][16384]
__device__ float2   g_G[16777216];    // W = combined conv output (packed)             [1024 pairs][16384]
__device__ uint32_t g_Rhi[16777216];  // real(ifft2) bf16 hi, packed channel pairs [B*128][16384]
__device__ uint32_t g_Rlo[16777216];  // residual bf16 lo
__device__ float    g_kern[8 * 49];   // per-batch 7x7 kernel
__device__ uint32_t g_Whi[32768];     // refine_w split: [c2=128][o=256]
__device__ uint32_t g_Wlo[32768];     // residuals

// ---------------- complex helpers ----------------
__device__ __forceinline__ float2 cadd(float2 a, float2 b) { return make_float2(a.x + b.x, a.y + b.y); }
__device__ __forceinline__ float2 csub(float2 a, float2 b) { return make_float2(a.x - b.x, a.y - b.y); }
__device__ __forceinline__ float2 cmul(float2 a, float2 b) {
  return make_float2(a.x * b.x - a.y * b.y, a.x * b.y + a.y * b.x);
}

// ---------------- bf16 split helpers ----------------
__device__ __forceinline__ void split2_bf16(float xe, float xo, uint32_t& hi, uint32_t& lo) {
  __nv_bfloat16 he = __float2bfloat16_rn(xe);
  __nv_bfloat16 ho = __float2bfloat16_rn(xo);
  float re = xe - __bfloat162float(he);
  float ro = xo - __bfloat162float(ho);
  __nv_bfloat16 le = __float2bfloat16_rn(re);
  __nv_bfloat16 lo16 = __float2bfloat16_rn(ro);
  hi = (uint32_t)__bfloat16_as_ushort(he) | ((uint32_t)__bfloat16_as_ushort(ho) << 16);
  lo = (uint32_t)__bfloat16_as_ushort(le) | ((uint32_t)__bfloat16_as_ushort(lo16) << 16);
}

// ---------------- warp-resident 128-pt DIF FFT ----------------
template<int SGN>
__device__ __forceinline__ void make_twiddles(int lane, float2 tw[7]) {
  const float TP = 6.283185307179586f * (float)SGN;
  float fr[7] = { lane / 128.f, (lane + 32) / 128.f, lane / 64.f,
                  (lane & 15) / 32.f, (lane & 7) / 16.f, (lane & 3) / 8.f, (lane & 1) / 4.f };
#pragma unroll
  for (int i = 0; i < 7; i++) {
    float s, c;
    sincosf(TP * fr[i], &s, &c);
    tw[i] = make_float2(c, s);
  }
}

__device__ __forceinline__ void fft128(float2 v[4], const float2 tw[7], int lane) {
  float2 t, u;
  t = v[0]; u = v[2]; v[0] = cadd(t, u); v[2] = cmul(csub(t, u), tw[0]);
  t = v[1]; u = v[3]; v[1] = cadd(t, u); v[3] = cmul(csub(t, u), tw[1]);
  t = v[0]; u = v[1]; v[0] = cadd(t, u); v[1] = cmul(csub(t, u), tw[2]);
  t = v[2]; u = v[3]; v[2] = cadd(t, u); v[3] = cmul(csub(t, u), tw[2]);
#pragma unroll
  for (int hi = 0; hi < 5; hi++) {
    int h = 16 >> hi;
    bool up = (lane & h) != 0;
#pragma unroll
    for (int s = 0; s < 4; s++) {
      float prx = __shfl_xor_sync(FULLMASK, v[s].x, h);
      float pry = __shfl_xor_sync(FULLMASK, v[s].y, h);
      float2 pr = make_float2(prx, pry);
      if (hi < 4) {
        v[s] = up ? cmul(csub(pr, v[s]), tw[3 + hi]) : cadd(v[s], pr);
      } else {
        v[s] = up ? csub(pr, v[s]) : cadd(v[s], pr);
      }
    }
  }
}

__device__ __forceinline__ int bitrev7(int p) { return (int)(__brev((unsigned)p) >> 25); }

// ---------------- forward FFT (channel-pair packed): x_low -> g_F (packed Z) ----------------
__global__ void __launch_bounds__(1024) fwd_fft_pair_kernel(const float* __restrict__ x) {
  extern __shared__ float sm[];
  float* sre = sm;
  float* sim = sm + 128 * 129;
  int pair = blockIdx.x;
  int ch1 = pair * 2, ch2 = ch1 + 1;
  int tid = threadIdx.x;
  int warp = tid >> 5, lane = tid & 31;
  float2 tw[7];
  make_twiddles<-1>(lane, tw);
  const float* x1 = x + (size_t)ch1 * 16384;
  const float* x2 = x + (size_t)ch2 * 16384;

  for (int r = warp; r < 128; r += 32) {
    float2 v[4];
#pragma unroll
    for (int s = 0; s < 4; s++) {
      int c = s * 32 + lane;
      v[s] = make_float2(x1[r * 128 + c] * 0.0078125f, x2[r * 128 + c] * 0.0078125f);
    }
    fft128(v, tw, lane);
#pragma unroll
    for (int s = 0; s < 4; s++) {
      int p = s * 32 + lane;
      int n = bitrev7(p) ^ 64;
      sre[r * 129 + n] = v[s].x;
      sim[r * 129 + n] = v[s].y;
    }
  }
  __syncthreads();
  for (int c = warp; c < 128; c += 32) {
    float2 v[4];
#pragma unroll
    for (int s = 0; s < 4; s++) {
      int p = s * 32 + lane;
      v[s] = make_float2(sre[p * 129 + c], sim[p * 129 + c]);
    }
    fft128(v, tw, lane);
#pragma unroll
    for (int s = 0; s < 4; s++) {
      int p = s * 32 + lane;
      int n = bitrev7(p) ^ 64;
      sre[n * 129 + c] = v[s].x;
      sim[n * 129 + c] = v[s].y;
    }
  }
  __syncthreads();
  // store packed Z directly (no Hermitian unpack)
  float2* Zb = g_F + (size_t)pair * 16384;
  for (int i = tid; i < 16384; i += 1024) {
    int r = i >> 7, c = i & 127;
    Zb[i] = make_float2(sre[r * 129 + c], sim[r * 129 + c]);
  }
}

// ---------------- tiny path: center magnitudes (unpacked from Z) -> MLP -> kernel ----------------
// Center 7x7 region [61..67]^2 is self-mirrored: mirror of (61+i,61+j) is (67-i,67-j).
__global__ void __launch_bounds__(256) mlp_kernel(const float* __restrict__ w1, const float* __restrict__ b1,
                                                  const float* __restrict__ w2, const float* __restrict__ b2) {
  int b = blockIdx.x;
  int t = threadIdx.x;
  __shared__ float part[49][4];
  __shared__ float flat[49];
  __shared__ float hbuf[32];
  __shared__ float prm[3];
  __shared__ float kv[49];
  __shared__ float ksum;

  if (t < 196) {
    int p = t >> 2, q = t & 3;
    int i = p / 7, j = p % 7;
    int im = 6 - i, jm = 6 - j;
    const float2* Zb = g_F + ((size_t)(b * 128 + q * 32)) * 16384;
    float s = 0.f;
#pragma unroll 4
    for (int pr = 0; pr < 32; pr++) {
      const float2* Zp = Zb + (size_t)pr * 16384;
      float2 z = Zp[(61 + i) * 128 + (61 + j)];
      float2 zm = Zp[(61 + im) * 128 + (61 + jm)];
      float e1 = z.x + zm.x, e2 = z.y - zm.y;   // Z + conj(Zmirror)  -> 2*F1
      float o1 = z.x - zm.x, o2 = z.y + zm.y;   // Z - conj(Zmirror)  -> 2i*F2
      s += 0.5f * (sqrtf(e1 * e1 + e2 * e2) + sqrtf(o1 * o1 + o2 * o2));
    }
    part[p][q] = s;
  }
  __syncthreads();
  if (t < 49) flat[t] = (part[t][0] + part[t][1] + part[t][2] + part[t][3]) * (1.f / 256.f);
  __syncthreads();
  if (t < 32) {
    float a = b1[t];
#pragma unroll
    for (int i = 0; i < 49; i++) a += flat[i] * w1[t * 49 + i];
    hbuf[t] = fmaxf(a, 0.f);
  }
  __syncthreads();
  if (t < 3) {
    float a = b2[t];
#pragma unroll
    for (int u = 0; u < 32; u++) a += hbuf[u] * w2[t * 32 + u];
    prm[t] = a;
  }
  __syncthreads();
  if (t < 49) {
    float theta = atan2f(prm[0], prm[1]) * 0.5f + (float)M_PI * 0.5f;
    float lam1 = expf(prm[2]);
    float lam2 = 1.f / (lam1 + 1e-8f);
    float ct = cosf(theta), st = sinf(theta);
    int i = t / 7, j = t % 7;
    float yy = (float)(i - 3), xx = (float)(j - 3);
    float xr = xx * ct + yy * st;
    float yr = -xx * st + yy * ct;
    kv[t] = expf(-(xr * xr / (2.f * lam1 * lam1) + yr * yr / (2.f * lam2 * lam2)));
  }
  __syncthreads();
  if (t == 0) {
    float s = 0.f;
    for (int i = 0; i < 49; i++) s += kv[i];
    ksum = s;
  }
  __syncthreads();
  if (t < 49) g_kern[b * 49 + t] = kv[t] / (ksum + 1e-8f);
}

// ---------------- packed conv: Z -> W (circular taps with pad/mirror half-weights) ----------------
// W(n) = sum_D k(D) * Z((n+D) mod 128) * 0.5*(a1*a2 + b1*b2)
//   a(n,d) = [0 <= n+d <= 127]                 (zero-pad indicator)
//   b(n,d) = n>=1 ? [1 <= n+d <= 128] : [d<=0] (mirror indicator)
// Interior (n in [4,124] both axes): weight == 1 -> plain circular conv.
__global__ void __launch_bounds__(256) wconv_kernel() {
  __shared__ float2 tile[22][134];
  __shared__ float kc[49];
  int pair = blockIdx.x;          // 0..1023
  int b = pair >> 7;
  int rBase = blockIdx.y * 16;
  int tid = threadIdx.x;
  if (tid < 49) kc[tid] = g_kern[b * 49 + tid];
  const float2* Zb = g_F + (size_t)pair * 16384;
  for (int idx = tid; idx < 22 * 134; idx += 256) {
    int tr = idx / 134, tc = idx % 134;
    int gr = (rBase - 3 + tr) & 127;   // circular halo
    int gc = (tc - 3) & 127;
    tile[tr][tc] = Zb[gr * 128 + gc];
  }
  __syncthreads();
  int w = tid & 127, rg = tid >> 7;
  bool colB = (w <= 3 || w >= 125);
  float2* Wb = g_G + (size_t)pair * 16384;
#pragma unroll
  for (int rr = 0; rr < 8; rr++) {
    int rl = rg * 8 + rr;
    int n1 = rBase + rl;
    bool rowB = (n1 <= 3 || n1 >= 125);
    float sre = 0.f, simv = 0.f;
    if (!(rowB || colB)) {
#pragma unroll
      for (int dy = 0; dy < 7; dy++)
#pragma unroll
        for (int dx = 0; dx < 7; dx++) {
          float2 in = tile[rl + dy][w + dx];
          float k = kc[dy * 7 + dx];
          sre += in.x * k;
          simv += in.y * k;
        }
    } else {
      for (int dy = 0; dy < 7; dy++) {
        int d1 = dy - 3, j1 = n1 + d1;
        bool a1 = (j1 >= 0 && j1 <= 127);
        bool b1 = (n1 >= 1) ? (j1 >= 1 && j1 <= 128) : (d1 <= 0);
        for (int dx = 0; dx < 7; dx++) {
          int d2 = dx - 3, j2 = w + d2;
          bool a2 = (j2 >= 0 && j2 <= 127);
          bool b2 = (w >= 1) ? (j2 >= 1 && j2 <= 128) : (d2 <= 0);
          float wt = 0.5f * ((float)(a1 && a2) + (float)(b1 && b2)) * kc[dy * 7 + dx];
          float2 in = tile[rl + dy][w + dx];
          sre += in.x * wt;
          simv += in.y * wt;
        }
      }
    }
    Wb[n1 * 128 + w] = make_float2(sre, simv);
  }
}

// ---------------- inverse FFT: W -> g_Rhi/g_Rlo (bf16 split) ----------------
__global__ void __launch_bounds__(1024) inv_fft_pair_kernel() {
  extern __shared__ float sm[];
  float* sre = sm;
  float* sim = sm + 128 * 129;
  int pair = blockIdx.x;
  int tid = threadIdx.x;
  int warp = tid >> 5, lane = tid & 31;
  float2 tw[7];
  make_twiddles<1>(lane, tw);
  const float2* Wb = g_G + (size_t)pair * 16384;

  for (int r = warp; r < 128; r += 32) {
    float2 v[4];
#pragma unroll
    for (int s = 0; s < 4; s++) {
      int cidx = (s * 32 + lane) ^ 64;      // ifftshift on cols
      float2 g = Wb[r * 128 + cidx];
      v[s] = make_float2(g.x * 0.0078125f, g.y * 0.0078125f);   // ortho 1/128
    }
    fft128(v, tw, lane);
#pragma unroll
    for (int s = 0; s < 4; s++) {
      int p = s * 32 + lane;
      int n = bitrev7(p);
      sre[r * 129 + n] = v[s].x;
      sim[r * 129 + n] = v[s].y;
    }
  }
  __syncthreads();
  for (int c = warp; c < 128; c += 32) {
    float2 v[4];
#pragma unroll
    for (int s = 0; s < 4; s++) {
      int ridx = (s * 32 + lane) ^ 64;      // ifftshift on rows
      v[s] = make_float2(sre[ridx * 129 + c], sim[ridx * 129 + c]);
    }
    fft128(v, tw, lane);
#pragma unroll
    for (int s = 0; s < 4; s++) {
      int p = s * 32 + lane;
      int n = bitrev7(p);
      sre[n * 129 + c] = v[s].x;
      sim[n * 129 + c] = v[s].y;
    }
  }
  __syncthreads();
  uint32_t* Rh = g_Rhi + (size_t)pair * 16384;
  uint32_t* Rl = g_Rlo + (size_t)pair * 16384;
  for (int i = tid; i < 16384; i += 1024) {
    int r = i >> 7, c = i & 127;
    uint32_t hi, lo;
    split2_bf16(sre[r * 129 + c], sim[r * 129 + c], hi, lo);
    Rh[i] = hi;
    Rl[i] = lo;
  }
}

// ---------------- weight prep: refine_w -> bf16-split packed channel pairs ----------------
__global__ void __launch_bounds__(256) wsplit_kernel(const float* __restrict__ W) {
  int idx = blockIdx.x * 256 + threadIdx.x;   // 0..32767
  int c2 = idx & 127, o = idx >> 7;
  float xe = W[o * 256 + 2 * c2];
  float xo = W[o * 256 + 2 * c2 + 1];
  uint32_t hi, lo;
  split2_bf16(xe, xo, hi, lo);
  g_Whi[c2 * 256 + o] = hi;
  g_Wlo[c2 * 256 + o] = lo;
}

// ---------------- bf16 MMA helper ----------------
__device__ __forceinline__ void mma_bf16(float* c, uint32_t a0, uint32_t a1, uint32_t a2, uint32_t a3,
                                         uint32_t b0, uint32_t b1) {
  asm volatile(
      "mma.sync.aligned.m16n8k16.row.col.f32.bf16.bf16.f32 "
      "{%0,%1,%2,%3}, {%4,%5,%6,%7}, {%8,%9}, {%0,%1,%2,%3};"
      : "+f"(c[0]), "+f"(c[1]), "+f"(c[2]), "+f"(c[3])
      : "r"(a0), "r"(a1), "r"(a2), "r"(a3), "r"(b0), "r"(b1));
}

// ---------------- channel mix GEMM (3-term bf16 tensor cores) + bilinear epilogue ----------------
__global__ void __launch_bounds__(256, 2) mix_kernel(const float* __restrict__ xh, float* __restrict__ out) {
  int b = blockIdx.z;
  int h = blockIdx.x;
  int oBase = blockIdx.y * 128;
  int tid = threadIdx.x;
  int warp = tid >> 5, lane = tid & 31;
  int lr = lane >> 2, lc = lane & 3;
  int warpO = (warp & 3) * 32;
  int warpW = (warp >> 2) * 64;

  __shared__ uint2 As[16][136];
  __shared__ uint2 Bs[16][136];

  float acc[2][8][4];
#pragma unroll
  for (int mt = 0; mt < 2; mt++)
#pragma unroll
    for (int nt = 0; nt < 8; nt++)
#pragma unroll
      for (int q = 0; q < 4; q++) acc[mt][nt][q] = 0.f;

  const uint32_t* RhB = g_Rhi + (size_t)b * 128 * 16384 + h * 128;
  const uint32_t* RlB = g_Rlo + (size_t)b * 128 * 16384 + h * 128;

  for (int kb = 0; kb < 8; kb++) {
    __syncthreads();
#pragma unroll
    for (int it = 0; it < 4; it++) {
      int item = it * 256 + tid;
      int o2 = item & 63;
      int k2 = item >> 6;
      uint2 ah = *(const uint2*)&g_Whi[(kb * 16 + k2) * 256 + oBase + o2 * 2];
      uint2 al = *(const uint2*)&g_Wlo[(kb * 16 + k2) * 256 + oBase + o2 * 2];
      *(uint4*)&As[k2][o2 * 2] = make_uint4(ah.x, al.x, ah.y, al.y);
      uint2 bh = *(const uint2*)&RhB[(size_t)(kb * 16 + k2) * 16384 + o2 * 2];
      uint2 bl = *(const uint2*)&RlB[(size_t)(kb * 16 + k2) * 16384 + o2 * 2];
      *(uint4*)&Bs[k2][o2 * 2] = make_uint4(bh.x, bl.x, bh.y, bl.y);
    }
    __syncthreads();
#pragma unroll
    for (int s = 0; s < 2; s++) {
      uint2 af[2][4];
#pragma unroll
      for (int mt = 0; mt < 2; mt++) {
#pragma unroll
        for (int rg = 0; rg < 4; rg++) {
          int k2 = s * 8 + lc + 4 * (rg >> 1);
          int o = warpO + mt * 16 + lr + 8 * (rg & 1);
          af[mt][rg] = As[k2][o];
        }
      }
      const uint2* bRow0 = &Bs[s * 8 + lc][warpW + lr];
      const uint2* bRow1 = &Bs[s * 8 + lc + 4][warpW + lr];
#pragma unroll
      for (int nt = 0; nt < 8; nt++) {
        uint2 b0 = bRow0[nt * 8];
        uint2 b1 = bRow1[nt * 8];
#pragma unroll
        for (int mt = 0; mt < 2; mt++) {
          mma_bf16(acc[mt][nt], af[mt][0].x, af[mt][1].x, af[mt][2].x, af[mt][3].x, b0.x, b1.x);
          mma_bf16(acc[mt][nt], af[mt][0].x, af[mt][1].x, af[mt][2].x, af[mt][3].x, b0.y, b1.y);
          mma_bf16(acc[mt][nt], af[mt][0].y, af[mt][1].y, af[mt][2].y, af[mt][3].y, b0.x, b1.x);
        }
      }
    }
  }

  float hin = 0.5f * (float)h - 0.25f;
  int hi0 = hin < 0.f ? 0 : (int)hin;
  float hf = hin < 0.f ? 0.f : hin - (float)hi0;
  int hi1 = hi0 + 1 < 64 ? hi0 + 1 : 63;

#pragma unroll
  for (int mt = 0; mt < 2; mt++) {
#pragma unroll
    for (int half = 0; half < 2; half++) {
      int o = oBase + warpO + mt * 16 + lr + 8 * half;
      const float* xb = xh + (size_t)(b * 256 + o) * 4096;
      const float* r0 = xb + hi0 * 64;
      const float* r1 = xb + hi1 * 64;
      float* orow = out + (size_t)(b * 256 + o) * 16384 + h * 128;
#pragma unroll
      for (int nt = 0; nt < 8; nt++) {
        int w0 = warpW + nt * 8 + 2 * lc;
        float v[2];
#pragma unroll
        for (int j = 0; j < 2; j++) {
          int w = w0 + j;
          float win = 0.5f * (float)w - 0.25f;
          int wi0 = win < 0.f ? 0 : (int)win;
          float wf = win < 0.f ? 0.f : win - (float)wi0;
          int wi1 = wi0 + 1 < 64 ? wi0 + 1 : 63;
          float top = r0[wi0] * (1.f - wf) + r0[wi1] * wf;
          float bot = r1[wi0] * (1.f - wf) + r1[wi1] * wf;
          v[j] = acc[mt][nt][half * 2 + j] + top * (1.f - hf) + bot * hf;
        }
        *(float2*)&orow[w0] = make_float2(v[0], v[1]);
      }
    }
  }
}

// ---------------- launch ----------------
extern "C" void kernel_launch(void* const* d_in, const int* in_sizes, int n_in,
                              void* d_out, int out_size) {
  const float* x_high = (const float*)d_in[0];
  const float* x_low = (const float*)d_in[1];
  const float* w1 = (const float*)d_in[2];
  const float* b1 = (const float*)d_in[3];
  const float* w2 = (const float*)d_in[4];
  const float* b2 = (const float*)d_in[5];
  const float* refine_w = (const float*)d_in[6];
  float* out = (float*)d_out;

  const int SMEM_FFT = 2 * 128 * 129 * 4;  // 132096 B
  cudaFuncSetAttribute((const void*)fwd_fft_pair_kernel, cudaFuncAttributeMaxDynamicSharedMemorySize, SMEM_FFT);
  cudaFuncSetAttribute((const void*)inv_fft_pair_kernel, cudaFuncAttributeMaxDynamicSharedMemorySize, SMEM_FFT);

  wsplit_kernel<<<128, 256>>>(refine_w);
  fwd_fft_pair_kernel<<<1024, 1024, SMEM_FFT>>>(x_low);
  mlp_kernel<<<8, 256>>>(w1, b1, w2, b2);
  wconv_kernel<<<dim3(1024, 8), 256>>>();
  inv_fft_pair_kernel<<<1024, 1024, SMEM_FFT>>>();
  mix_kernel<<<dim3(128, 2, 8), 256>>>(x_high, out);
}

// round 11
// speedup vs baseline: 1.2799x; 1.2799x over previous
#include <cuda_runtime.h>
#include <cuda_bf16.h>
#include <math.h>
#include <stdint.h>

#ifndef M_PI
#define M_PI 3.14159265358979323846
#endif

#define FULLMASK 0xffffffffu

// ---------------- scratch (static device globals; no allocations) ----------------
__device__ float2   g_F[16777216];    // packed spectrum Z = fft2(x1 + i x2), shifted  [1024 pairs][16384]
__device__ float2   g_G[16777216];    // W = combined conv output (packed)             [1024 pairs][16384]
__device__ uint32_t g_Rhi[16777216];  // real(ifft2) bf16 hi, packed channel pairs [B*128][16384]
__device__ uint32_t g_Rlo[16777216];  // residual bf16 lo
__device__ float    g_kern[8 * 49];   // per-batch 7x7 kernel
__device__ uint32_t g_Whi[32768];     // refine_w split: [c2=128][o=256]
__device__ uint32_t g_Wlo[32768];     // residuals

// ---------------- complex helpers ----------------
__device__ __forceinline__ float2 cadd(float2 a, float2 b) { return make_float2(a.x + b.x, a.y + b.y); }
__device__ __forceinline__ float2 csub(float2 a, float2 b) { return make_float2(a.x - b.x, a.y - b.y); }
__device__ __forceinline__ float2 cmul(float2 a, float2 b) {
  return make_float2(a.x * b.x - a.y * b.y, a.x * b.y + a.y * b.x);
}

// ---------------- bf16 split helpers ----------------
__device__ __forceinline__ void split2_bf16(float xe, float xo, uint32_t& hi, uint32_t& lo) {
  __nv_bfloat16 he = __float2bfloat16_rn(xe);
  __nv_bfloat16 ho = __float2bfloat16_rn(xo);
  float re = xe - __bfloat162float(he);
  float ro = xo - __bfloat162float(ho);
  __nv_bfloat16 le = __float2bfloat16_rn(re);
  __nv_bfloat16 lo16 = __float2bfloat16_rn(ro);
  hi = (uint32_t)__bfloat16_as_ushort(he) | ((uint32_t)__bfloat16_as_ushort(ho) << 16);
  lo = (uint32_t)__bfloat16_as_ushort(le) | ((uint32_t)__bfloat16_as_ushort(lo16) << 16);
}

// ---------------- warp-resident 128-pt DIF FFT ----------------
template<int SGN>
__device__ __forceinline__ void make_twiddles(int lane, float2 tw[7]) {
  const float TP = 6.283185307179586f * (float)SGN;
  float fr[7] = { lane / 128.f, (lane + 32) / 128.f, lane / 64.f,
                  (lane & 15) / 32.f, (lane & 7) / 16.f, (lane & 3) / 8.f, (lane & 1) / 4.f };
#pragma unroll
  for (int i = 0; i < 7; i++) {
    float s, c;
    sincosf(TP * fr[i], &s, &c);
    tw[i] = make_float2(c, s);
  }
}

__device__ __forceinline__ void fft128(float2 v[4], const float2 tw[7], int lane) {
  float2 t, u;
  t = v[0]; u = v[2]; v[0] = cadd(t, u); v[2] = cmul(csub(t, u), tw[0]);
  t = v[1]; u = v[3]; v[1] = cadd(t, u); v[3] = cmul(csub(t, u), tw[1]);
  t = v[0]; u = v[1]; v[0] = cadd(t, u); v[1] = cmul(csub(t, u), tw[2]);
  t = v[2]; u = v[3]; v[2] = cadd(t, u); v[3] = cmul(csub(t, u), tw[2]);
#pragma unroll
  for (int hi = 0; hi < 5; hi++) {
    int h = 16 >> hi;
    bool up = (lane & h) != 0;
#pragma unroll
    for (int s = 0; s < 4; s++) {
      float prx = __shfl_xor_sync(FULLMASK, v[s].x, h);
      float pry = __shfl_xor_sync(FULLMASK, v[s].y, h);
      float2 pr = make_float2(prx, pry);
      if (hi < 4) {
        v[s] = up ? cmul(csub(pr, v[s]), tw[3 + hi]) : cadd(v[s], pr);
      } else {
        v[s] = up ? csub(pr, v[s]) : cadd(v[s], pr);
      }
    }
  }
}

__device__ __forceinline__ int bitrev7(int p) { return (int)(__brev((unsigned)p) >> 25); }

// ---------------- forward FFT (channel-pair packed): x_low -> g_F (packed Z) ----------------
__global__ void __launch_bounds__(1024) fwd_fft_pair_kernel(const float* __restrict__ x) {
  extern __shared__ float sm[];
  float* sre = sm;
  float* sim = sm + 128 * 129;
  int pair = blockIdx.x;
  int ch1 = pair * 2, ch2 = ch1 + 1;
  int tid = threadIdx.x;
  int warp = tid >> 5, lane = tid & 31;
  float2 tw[7];
  make_twiddles<-1>(lane, tw);
  const float* x1 = x + (size_t)ch1 * 16384;
  const float* x2 = x + (size_t)ch2 * 16384;

  for (int r = warp; r < 128; r += 32) {
    float2 v[4];
#pragma unroll
    for (int s = 0; s < 4; s++) {
      int c = s * 32 + lane;
      v[s] = make_float2(x1[r * 128 + c] * 0.0078125f, x2[r * 128 + c] * 0.0078125f);
    }
    fft128(v, tw, lane);
#pragma unroll
    for (int s = 0; s < 4; s++) {
      int p = s * 32 + lane;
      int n = bitrev7(p) ^ 64;
      sre[r * 129 + n] = v[s].x;
      sim[r * 129 + n] = v[s].y;
    }
  }
  __syncthreads();
  for (int c = warp; c < 128; c += 32) {
    float2 v[4];
#pragma unroll
    for (int s = 0; s < 4; s++) {
      int p = s * 32 + lane;
      v[s] = make_float2(sre[p * 129 + c], sim[p * 129 + c]);
    }
    fft128(v, tw, lane);
#pragma unroll
    for (int s = 0; s < 4; s++) {
      int p = s * 32 + lane;
      int n = bitrev7(p) ^ 64;
      sre[n * 129 + c] = v[s].x;
      sim[n * 129 + c] = v[s].y;
    }
  }
  __syncthreads();
  float2* Zb = g_F + (size_t)pair * 16384;
  for (int i = tid; i < 16384; i += 1024) {
    int r = i >> 7, c = i & 127;
    Zb[i] = make_float2(sre[r * 129 + c], sim[r * 129 + c]);
  }
}

// ---------------- tiny path: center magnitudes (unpacked from Z) -> MLP -> kernel ----------------
__global__ void __launch_bounds__(256) mlp_kernel(const float* __restrict__ w1, const float* __restrict__ b1,
                                                  const float* __restrict__ w2, const float* __restrict__ b2) {
  int b = blockIdx.x;
  int t = threadIdx.x;
  __shared__ float part[49][4];
  __shared__ float flat[49];
  __shared__ float hbuf[32];
  __shared__ float prm[3];
  __shared__ float kv[49];
  __shared__ float ksum;

  if (t < 196) {
    int p = t >> 2, q = t & 3;
    int i = p / 7, j = p % 7;
    int im = 6 - i, jm = 6 - j;
    const float2* Zb = g_F + ((size_t)(b * 128 + q * 32)) * 16384;
    float s = 0.f;
#pragma unroll 4
    for (int pr = 0; pr < 32; pr++) {
      const float2* Zp = Zb + (size_t)pr * 16384;
      float2 z = Zp[(61 + i) * 128 + (61 + j)];
      float2 zm = Zp[(61 + im) * 128 + (61 + jm)];
      float e1 = z.x + zm.x, e2 = z.y - zm.y;   // Z + conj(Zmirror)  -> 2*F1
      float o1 = z.x - zm.x, o2 = z.y + zm.y;   // Z - conj(Zmirror)  -> 2i*F2
      s += 0.5f * (sqrtf(e1 * e1 + e2 * e2) + sqrtf(o1 * o1 + o2 * o2));
    }
    part[p][q] = s;
  }
  __syncthreads();
  if (t < 49) flat[t] = (part[t][0] + part[t][1] + part[t][2] + part[t][3]) * (1.f / 256.f);
  __syncthreads();
  if (t < 32) {
    float a = b1[t];
#pragma unroll
    for (int i = 0; i < 49; i++) a += flat[i] * w1[t * 49 + i];
    hbuf[t] = fmaxf(a, 0.f);
  }
  __syncthreads();
  if (t < 3) {
    float a = b2[t];
#pragma unroll
    for (int u = 0; u < 32; u++) a += hbuf[u] * w2[t * 32 + u];
    prm[t] = a;
  }
  __syncthreads();
  if (t < 49) {
    float theta = atan2f(prm[0], prm[1]) * 0.5f + (float)M_PI * 0.5f;
    float lam1 = expf(prm[2]);
    float lam2 = 1.f / (lam1 + 1e-8f);
    float ct = cosf(theta), st = sinf(theta);
    int i = t / 7, j = t % 7;
    float yy = (float)(i - 3), xx = (float)(j - 3);
    float xr = xx * ct + yy * st;
    float yr = -xx * st + yy * ct;
    kv[t] = expf(-(xr * xr / (2.f * lam1 * lam1) + yr * yr / (2.f * lam2 * lam2)));
  }
  __syncthreads();
  if (t == 0) {
    float s = 0.f;
    for (int i = 0; i < 49; i++) s += kv[i];
    ksum = s;
  }
  __syncthreads();
  if (t < 49) g_kern[b * 49 + t] = kv[t] / (ksum + 1e-8f);
}

// ---------------- circular conv (interior-exact): Z -> W, no boundary logic at all ----------------
__global__ void __launch_bounds__(256) cconv_kernel() {
  __shared__ float2 tile[22][134];
  __shared__ float kc[49];
  int pair = blockIdx.x;          // 0..1023
  int b = pair >> 7;
  int rBase = blockIdx.y * 16;
  int tid = threadIdx.x;
  if (tid < 49) kc[tid] = g_kern[b * 49 + tid];
  const float2* Zb = g_F + (size_t)pair * 16384;
  for (int idx = tid; idx < 22 * 134; idx += 256) {
    int tr = idx / 134, tc = idx % 134;
    int gr = (rBase - 3 + tr) & 127;   // circular halo
    int gc = (tc - 3) & 127;
    tile[tr][tc] = Zb[gr * 128 + gc];
  }
  __syncthreads();
  int w = tid & 127, rg = tid >> 7;
  float2* Wb = g_G + (size_t)pair * 16384;
#pragma unroll
  for (int rr = 0; rr < 8; rr++) {
    int rl = rg * 8 + rr;
    float sre = 0.f, simv = 0.f;
#pragma unroll
    for (int dy = 0; dy < 7; dy++)
#pragma unroll
      for (int dx = 0; dx < 7; dx++) {
        float2 in = tile[rl + dy][w + dx];
        float k = kc[dy * 7 + dx];
        sre += in.x * k;
        simv += in.y * k;
      }
    Wb[(rBase + rl) * 128 + w] = make_float2(sre, simv);
  }
}

// ---------------- boundary fixup: recompute 1743-pixel frame with exact pad/mirror weights ----------------
// W(n) = sum_D k(D) * Z((n+D) mod 128) * 0.5*(a1*a2 + b1*b2)
//   a(n,d) = [0 <= n+d <= 127]                 (zero-pad indicator)
//   b(n,d) = n>=1 ? [1 <= n+d <= 128] : [d<=0] (mirror indicator)
__global__ void __launch_bounds__(256) bconv_kernel() {
  __shared__ float kc[49];
  int pair = blockIdx.x;          // 0..1023
  int b = pair >> 7;
  int tid = threadIdx.x;
  if (tid < 49) kc[tid] = g_kern[b * 49 + tid];
  __syncthreads();
  const float2* Zb = g_F + (size_t)pair * 16384;
  float2* Wb = g_G + (size_t)pair * 16384;
  // frame: rows {0..3,125..127} x all cols (896) + rows 4..124 x cols {0..3,125..127} (847)
  for (int idx = tid; idx < 1743; idx += 256) {
    int n1, n2;
    if (idx < 896) {
      int r = idx >> 7;
      n1 = (r < 4) ? r : (121 + r);     // 0..3, 125..127
      n2 = idx & 127;
    } else {
      int j = idx - 896;
      n1 = 4 + j / 7;                   // 4..124
      int c = j % 7;
      n2 = (c < 4) ? c : (121 + c);     // 0..3, 125..127
    }
    float wy[7], wz[7], vy[7], vz[7];   // per-axis a/b indicators
#pragma unroll
    for (int d = 0; d < 7; d++) {
      int dd = d - 3;
      int j1 = n1 + dd, j2 = n2 + dd;
      wy[d] = (j1 >= 0 && j1 <= 127) ? 1.f : 0.f;
      vy[d] = ((n1 >= 1) ? (j1 >= 1 && j1 <= 128) : (dd <= 0)) ? 1.f : 0.f;
      wz[d] = (j2 >= 0 && j2 <= 127) ? 1.f : 0.f;
      vz[d] = ((n2 >= 1) ? (j2 >= 1 && j2 <= 128) : (dd <= 0)) ? 1.f : 0.f;
    }
    float sre = 0.f, simv = 0.f;
#pragma unroll
    for (int dy = 0; dy < 7; dy++) {
      int r = (n1 + dy - 3) & 127;
      const float2* Zr = Zb + r * 128;
#pragma unroll
      for (int dx = 0; dx < 7; dx++) {
        float wt = 0.5f * (wy[dy] * wz[dx] + vy[dy] * vz[dx]) * kc[dy * 7 + dx];
        float2 in = Zr[(n2 + dx - 3) & 127];
        sre += in.x * wt;
        simv += in.y * wt;
      }
    }
    Wb[n1 * 128 + n2] = make_float2(sre, simv);
  }
}

// ---------------- inverse FFT: W -> g_Rhi/g_Rlo (bf16 split) ----------------
__global__ void __launch_bounds__(1024) inv_fft_pair_kernel() {
  extern __shared__ float sm[];
  float* sre = sm;
  float* sim = sm + 128 * 129;
  int pair = blockIdx.x;
  int tid = threadIdx.x;
  int warp = tid >> 5, lane = tid & 31;
  float2 tw[7];
  make_twiddles<1>(lane, tw);
  const float2* Wb = g_G + (size_t)pair * 16384;

  for (int r = warp; r < 128; r += 32) {
    float2 v[4];
#pragma unroll
    for (int s = 0; s < 4; s++) {
      int cidx = (s * 32 + lane) ^ 64;      // ifftshift on cols
      float2 g = Wb[r * 128 + cidx];
      v[s] = make_float2(g.x * 0.0078125f, g.y * 0.0078125f);   // ortho 1/128
    }
    fft128(v, tw, lane);
#pragma unroll
    for (int s = 0; s < 4; s++) {
      int p = s * 32 + lane;
      int n = bitrev7(p);
      sre[r * 129 + n] = v[s].x;
      sim[r * 129 + n] = v[s].y;
    }
  }
  __syncthreads();
  for (int c = warp; c < 128; c += 32) {
    float2 v[4];
#pragma unroll
    for (int s = 0; s < 4; s++) {
      int ridx = (s * 32 + lane) ^ 64;      // ifftshift on rows
      v[s] = make_float2(sre[ridx * 129 + c], sim[ridx * 129 + c]);
    }
    fft128(v, tw, lane);
#pragma unroll
    for (int s = 0; s < 4; s++) {
      int p = s * 32 + lane;
      int n = bitrev7(p);
      sre[n * 129 + c] = v[s].x;
      sim[n * 129 + c] = v[s].y;
    }
  }
  __syncthreads();
  uint32_t* Rh = g_Rhi + (size_t)pair * 16384;
  uint32_t* Rl = g_Rlo + (size_t)pair * 16384;
  for (int i = tid; i < 16384; i += 1024) {
    int r = i >> 7, c = i & 127;
    uint32_t hi, lo;
    split2_bf16(sre[r * 129 + c], sim[r * 129 + c], hi, lo);
    Rh[i] = hi;
    Rl[i] = lo;
  }
}

// ---------------- weight prep: refine_w -> bf16-split packed channel pairs ----------------
__global__ void __launch_bounds__(256) wsplit_kernel(const float* __restrict__ W) {
  int idx = blockIdx.x * 256 + threadIdx.x;   // 0..32767
  int c2 = idx & 127, o = idx >> 7;
  float xe = W[o * 256 + 2 * c2];
  float xo = W[o * 256 + 2 * c2 + 1];
  uint32_t hi, lo;
  split2_bf16(xe, xo, hi, lo);
  g_Whi[c2 * 256 + o] = hi;
  g_Wlo[c2 * 256 + o] = lo;
}

// ---------------- bf16 MMA helper ----------------
__device__ __forceinline__ void mma_bf16(float* c, uint32_t a0, uint32_t a1, uint32_t a2, uint32_t a3,
                                         uint32_t b0, uint32_t b1) {
  asm volatile(
      "mma.sync.aligned.m16n8k16.row.col.f32.bf16.bf16.f32 "
      "{%0,%1,%2,%3}, {%4,%5,%6,%7}, {%8,%9}, {%0,%1,%2,%3};"
      : "+f"(c[0]), "+f"(c[1]), "+f"(c[2]), "+f"(c[3])
      : "r"(a0), "r"(a1), "r"(a2), "r"(a3), "r"(b0), "r"(b1));
}

// ---------------- channel mix GEMM (3-term bf16 tensor cores) + bilinear epilogue ----------------
__global__ void __launch_bounds__(256, 2) mix_kernel(const float* __restrict__ xh, float* __restrict__ out) {
  int b = blockIdx.z;
  int h = blockIdx.x;
  int oBase = blockIdx.y * 128;
  int tid = threadIdx.x;
  int warp = tid >> 5, lane = tid & 31;
  int lr = lane >> 2, lc = lane & 3;
  int warpO = (warp & 3) * 32;
  int warpW = (warp >> 2) * 64;

  __shared__ uint2 As[16][136];
  __shared__ uint2 Bs[16][136];

  float acc[2][8][4];
#pragma unroll
  for (int mt = 0; mt < 2; mt++)
#pragma unroll
    for (int nt = 0; nt < 8; nt++)
#pragma unroll
      for (int q = 0; q < 4; q++) acc[mt][nt][q] = 0.f;

  const uint32_t* RhB = g_Rhi + (size_t)b * 128 * 16384 + h * 128;
  const uint32_t* RlB = g_Rlo + (size_t)b * 128 * 16384 + h * 128;

  for (int kb = 0; kb < 8; kb++) {
    __syncthreads();
#pragma unroll
    for (int it = 0; it < 4; it++) {
      int item = it * 256 + tid;
      int o2 = item & 63;
      int k2 = item >> 6;
      uint2 ah = *(const uint2*)&g_Whi[(kb * 16 + k2) * 256 + oBase + o2 * 2];
      uint2 al = *(const uint2*)&g_Wlo[(kb * 16 + k2) * 256 + oBase + o2 * 2];
      *(uint4*)&As[k2][o2 * 2] = make_uint4(ah.x, al.x, ah.y, al.y);
      uint2 bh = *(const uint2*)&RhB[(size_t)(kb * 16 + k2) * 16384 + o2 * 2];
      uint2 bl = *(const uint2*)&RlB[(size_t)(kb * 16 + k2) * 16384 + o2 * 2];
      *(uint4*)&Bs[k2][o2 * 2] = make_uint4(bh.x, bl.x, bh.y, bl.y);
    }
    __syncthreads();
#pragma unroll
    for (int s = 0; s < 2; s++) {
      uint2 af[2][4];
#pragma unroll
      for (int mt = 0; mt < 2; mt++) {
#pragma unroll
        for (int rg = 0; rg < 4; rg++) {
          int k2 = s * 8 + lc + 4 * (rg >> 1);
          int o = warpO + mt * 16 + lr + 8 * (rg & 1);
          af[mt][rg] = As[k2][o];
        }
      }
      const uint2* bRow0 = &Bs[s * 8 + lc][warpW + lr];
      const uint2* bRow1 = &Bs[s * 8 + lc + 4][warpW + lr];
#pragma unroll
      for (int nt = 0; nt < 8; nt++) {
        uint2 b0 = bRow0[nt * 8];
        uint2 b1 = bRow1[nt * 8];
#pragma unroll
        for (int mt = 0; mt < 2; mt++) {
          mma_bf16(acc[mt][nt], af[mt][0].x, af[mt][1].x, af[mt][2].x, af[mt][3].x, b0.x, b1.x);
          mma_bf16(acc[mt][nt], af[mt][0].x, af[mt][1].x, af[mt][2].x, af[mt][3].x, b0.y, b1.y);
          mma_bf16(acc[mt][nt], af[mt][0].y, af[mt][1].y, af[mt][2].y, af[mt][3].y, b0.x, b1.x);
        }
      }
    }
  }

  float hin = 0.5f * (float)h - 0.25f;
  int hi0 = hin < 0.f ? 0 : (int)hin;
  float hf = hin < 0.f ? 0.f : hin - (float)hi0;
  int hi1 = hi0 + 1 < 64 ? hi0 + 1 : 63;

#pragma unroll
  for (int mt = 0; mt < 2; mt++) {
#pragma unroll
    for (int half = 0; half < 2; half++) {
      int o = oBase + warpO + mt * 16 + lr + 8 * half;
      const float* xb = xh + (size_t)(b * 256 + o) * 4096;
      const float* r0 = xb + hi0 * 64;
      const float* r1 = xb + hi1 * 64;
      float* orow = out + (size_t)(b * 256 + o) * 16384 + h * 128;
#pragma unroll
      for (int nt = 0; nt < 8; nt++) {
        int w0 = warpW + nt * 8 + 2 * lc;
        float v[2];
#pragma unroll
        for (int j = 0; j < 2; j++) {
          int w = w0 + j;
          float win = 0.5f * (float)w - 0.25f;
          int wi0 = win < 0.f ? 0 : (int)win;
          float wf = win < 0.f ? 0.f : win - (float)wi0;
          int wi1 = wi0 + 1 < 64 ? wi0 + 1 : 63;
          float top = r0[wi0] * (1.f - wf) + r0[wi1] * wf;
          float bot = r1[wi0] * (1.f - wf) + r1[wi1] * wf;
          v[j] = acc[mt][nt][half * 2 + j] + top * (1.f - hf) + bot * hf;
        }
        *(float2*)&orow[w0] = make_float2(v[0], v[1]);
      }
    }
  }
}

// ---------------- launch ----------------
extern "C" void kernel_launch(void* const* d_in, const int* in_sizes, int n_in,
                              void* d_out, int out_size) {
  const float* x_high = (const float*)d_in[0];
  const float* x_low = (const float*)d_in[1];
  const float* w1 = (const float*)d_in[2];
  const float* b1 = (const float*)d_in[3];
  const float* w2 = (const float*)d_in[4];
  const float* b2 = (const float*)d_in[5];
  const float* refine_w = (const float*)d_in[6];
  float* out = (float*)d_out;

  const int SMEM_FFT = 2 * 128 * 129 * 4;  // 132096 B
  cudaFuncSetAttribute((const void*)fwd_fft_pair_kernel, cudaFuncAttributeMaxDynamicSharedMemorySize, SMEM_FFT);
  cudaFuncSetAttribute((const void*)inv_fft_pair_kernel, cudaFuncAttributeMaxDynamicSharedMemorySize, SMEM_FFT);

  wsplit_kernel<<<128, 256>>>(refine_w);
  fwd_fft_pair_kernel<<<1024, 1024, SMEM_FFT>>>(x_low);
  mlp_kernel<<<8, 256>>>(w1, b1, w2, b2);
  cconv_kernel<<<dim3(1024, 8), 256>>>();
  bconv_kernel<<<1024, 256>>>();
  inv_fft_pair_kernel<<<1024, 1024, SMEM_FFT>>>();
  mix_kernel<<<dim3(128, 2, 8), 256>>>(x_high, out);
}